// round 3
// baseline (speedup 1.0000x reference)
#include <cuda_runtime.h>
#include <cstddef>

// Feature_Embedding (FFM pairwise field interactions)
// x: (4096,16) int32; W: (16,100000,64) fp32; out: (4096, 8704) fp32.
// DRAM traffic is at the compulsory floor (~333MB measured); this round
// targets MLP: uniform datapath (diag = pair * ones), 3 units (6 LDG.128)
// batched in flight per thread.

constexpr int F_FIELDS = 16;
constexpr int V_VOCAB  = 100000;
constexpr int N_UNITS  = 136;            // 120 pairs + 16 diag
constexpr int OUT_F4   = N_UNITS * 16;   // 2176 float4 per row
constexpr int ROW_F4   = 16;             // 64 floats = 16 float4

// c_unit[u] = i | (j<<8) | (B_is_ones<<16) | (pad<<17)
//   u <120 : pair (i<j), A=W[j,x[i]], B=W[i,x[j]]
//   120-135: diag f=u-120 (i=j=f), A=W[f,x[f]], B=ones
//   136-143: padding, A=B=ones, no store
__constant__ unsigned int c_unit[144] = {
    0x0100,0x0200,0x0300,0x0400,0x0500,0x0600,0x0700,0x0800,
    0x0900,0x0A00,0x0B00,0x0C00,0x0D00,0x0E00,0x0F00,
    0x0201,0x0301,0x0401,0x0501,0x0601,0x0701,0x0801,0x0901,
    0x0A01,0x0B01,0x0C01,0x0D01,0x0E01,0x0F01,
    0x0302,0x0402,0x0502,0x0602,0x0702,0x0802,0x0902,0x0A02,
    0x0B02,0x0C02,0x0D02,0x0E02,0x0F02,
    0x0403,0x0503,0x0603,0x0703,0x0803,0x0903,0x0A03,0x0B03,
    0x0C03,0x0D03,0x0E03,0x0F03,
    0x0504,0x0604,0x0704,0x0804,0x0904,0x0A04,0x0B04,0x0C04,
    0x0D04,0x0E04,0x0F04,
    0x0605,0x0705,0x0805,0x0905,0x0A05,0x0B05,0x0C05,0x0D05,
    0x0E05,0x0F05,
    0x0706,0x0806,0x0906,0x0A06,0x0B06,0x0C06,0x0D06,0x0E06,0x0F06,
    0x0807,0x0907,0x0A07,0x0B07,0x0C07,0x0D07,0x0E07,0x0F07,
    0x0908,0x0A08,0x0B08,0x0C08,0x0D08,0x0E08,0x0F08,
    0x0A09,0x0B09,0x0C09,0x0D09,0x0E09,0x0F09,
    0x0B0A,0x0C0A,0x0D0A,0x0E0A,0x0F0A,
    0x0C0B,0x0D0B,0x0E0B,0x0F0B,
    0x0D0C,0x0E0C,0x0F0C,
    0x0E0D,0x0F0D,
    0x0F0E,
    // diag
    0x10000,0x10101,0x10202,0x10303,0x10404,0x10505,0x10606,0x10707,
    0x10808,0x10909,0x10A0A,0x10B0B,0x10C0C,0x10D0D,0x10E0E,0x10F0F,
    // pad
    0x30000,0x30000,0x30000,0x30000,0x30000,0x30000,0x30000,0x30000
};

__device__ __align__(256) float4 g_ones4[16] = {
    {1.f,1.f,1.f,1.f},{1.f,1.f,1.f,1.f},{1.f,1.f,1.f,1.f},{1.f,1.f,1.f,1.f},
    {1.f,1.f,1.f,1.f},{1.f,1.f,1.f,1.f},{1.f,1.f,1.f,1.f},{1.f,1.f,1.f,1.f},
    {1.f,1.f,1.f,1.f},{1.f,1.f,1.f,1.f},{1.f,1.f,1.f,1.f},{1.f,1.f,1.f,1.f},
    {1.f,1.f,1.f,1.f},{1.f,1.f,1.f,1.f},{1.f,1.f,1.f,1.f},{1.f,1.f,1.f,1.f}
};

__global__ __launch_bounds__(256, 5)
void ffm_interact_kernel(const int* __restrict__ x,
                         const float* __restrict__ W,
                         float* __restrict__ out)
{
    const int tid  = threadIdx.x;
    const int b    = blockIdx.x;
    const int lane = tid & (ROW_F4 - 1);   // float4 lane within 64-dim row
    const int w    = tid >> 4;             // unit stripe base (0..15)
    const int lid  = tid & 31;

    // each warp loads the 16-field index row; broadcast via shuffle
    const int myx = __ldg(&x[b * F_FIELDS + (lid & 15)]);

    const float4* __restrict__ W4 = reinterpret_cast<const float4*>(W);
    const float4* __restrict__ ones = g_ones4 + lane;
    float4* __restrict__ out4 =
        reinterpret_cast<float4*>(out) + (size_t)b * OUT_F4;

    #pragma unroll
    for (int g = 0; g < 3; ++g) {
        float4 va[3], vb[3];
        int    uu[3];
        // address gen + load: 6 independent LDG.128 in flight
        #pragma unroll
        for (int k = 0; k < 3; ++k) {
            const int u = w + (g * 3 + k) * 16;
            uu[k] = u;
            const unsigned int pt = c_unit[u];
            const int i = (int)(pt & 0xFF);
            const int j = (int)((pt >> 8) & 0xFF);
            const int xi = __shfl_sync(0xFFFFFFFFu, myx, i);
            const int xj = __shfl_sync(0xFFFFFFFFu, myx, j);
            const float4* pa = (pt & 0x20000u) ? ones
                : (W4 + ((size_t)j * V_VOCAB + (size_t)xi) * ROW_F4 + lane);
            const float4* pb = (pt & 0x10000u) ? ones
                : (W4 + ((size_t)i * V_VOCAB + (size_t)xj) * ROW_F4 + lane);
            va[k] = __ldg(pa);
            vb[k] = __ldg(pb);
        }
        // consume + store
        #pragma unroll
        for (int k = 0; k < 3; ++k) {
            float4 r;
            r.x = va[k].x * vb[k].x;
            r.y = va[k].y * vb[k].y;
            r.z = va[k].z * vb[k].z;
            r.w = va[k].w * vb[k].w;
            if (uu[k] < N_UNITS) {
                __stcs(&out4[(size_t)uu[k] * ROW_F4 + lane], r);
            }
        }
    }
}

extern "C" void kernel_launch(void* const* d_in, const int* in_sizes, int n_in,
                              void* d_out, int out_size)
{
    const int*   x = (const int*)d_in[0];
    const float* W = (const float*)d_in[1];
    float*       o = (float*)d_out;

    const int B = in_sizes[0] / F_FIELDS;   // 4096

    ffm_interact_kernel<<<B, 256>>>(x, W, o);
}

// round 4
// speedup vs baseline: 1.0021x; 1.0021x over previous
#include <cuda_runtime.h>
#include <cstddef>

// Feature_Embedding (FFM pairwise field interactions)
// x: (4096,16) int32; W: (16,100000,64) fp32; out: (4096, 8704) fp32.
// Traffic is at the compulsory DRAM floor (~331MB measured). This round:
// finer block granularity (2 blocks/row, 68 units each) + occ-8 to smooth
// wave-tail quantization; everything else kept minimal.

constexpr int F_FIELDS = 16;
constexpr int V_VOCAB  = 100000;
constexpr int N_PAIRS  = 120;
constexpr int N_UNITS  = 136;            // 120 pairs + 16 diag
constexpr int OUT_F4   = N_UNITS * 16;   // 2176 float4 per row
constexpr int ROW_F4   = 16;             // 64 floats = 16 float4
constexpr int UNITS_PER_BLK = 68;        // N_UNITS / 2

// c_pair[u] = i | (j<<8), triu k=1 row-major
__constant__ unsigned short c_pair[N_PAIRS] = {
    0x0100,0x0200,0x0300,0x0400,0x0500,0x0600,0x0700,0x0800,
    0x0900,0x0A00,0x0B00,0x0C00,0x0D00,0x0E00,0x0F00,
    0x0201,0x0301,0x0401,0x0501,0x0601,0x0701,0x0801,0x0901,
    0x0A01,0x0B01,0x0C01,0x0D01,0x0E01,0x0F01,
    0x0302,0x0402,0x0502,0x0602,0x0702,0x0802,0x0902,0x0A02,
    0x0B02,0x0C02,0x0D02,0x0E02,0x0F02,
    0x0403,0x0503,0x0603,0x0703,0x0803,0x0903,0x0A03,0x0B03,
    0x0C03,0x0D03,0x0E03,0x0F03,
    0x0504,0x0604,0x0704,0x0804,0x0904,0x0A04,0x0B04,0x0C04,
    0x0D04,0x0E04,0x0F04,
    0x0605,0x0705,0x0805,0x0905,0x0A05,0x0B05,0x0C05,0x0D05,
    0x0E05,0x0F05,
    0x0706,0x0806,0x0906,0x0A06,0x0B06,0x0C06,0x0D06,0x0E06,0x0F06,
    0x0807,0x0907,0x0A07,0x0B07,0x0C07,0x0D07,0x0E07,0x0F07,
    0x0908,0x0A08,0x0B08,0x0C08,0x0D08,0x0E08,0x0F08,
    0x0A09,0x0B09,0x0C09,0x0D09,0x0E09,0x0F09,
    0x0B0A,0x0C0A,0x0D0A,0x0E0A,0x0F0A,
    0x0C0B,0x0D0B,0x0E0B,0x0F0B,
    0x0D0C,0x0E0C,0x0F0C,
    0x0E0D,0x0F0D,
    0x0F0E
};

__global__ __launch_bounds__(256, 8)
void ffm_interact_kernel(const int* __restrict__ x,
                         const float* __restrict__ W,
                         float* __restrict__ out)
{
    const int tid  = threadIdx.x;
    const int b    = blockIdx.x;
    const int base = blockIdx.y * UNITS_PER_BLK;   // 0 or 68
    const int lane = tid & (ROW_F4 - 1);           // float4 lane within row
    const int w    = tid >> 4;                     // unit stripe (0..15)
    const int lid  = tid & 31;

    // each warp loads the 16-field index row; broadcast via shuffle
    const int myx = __ldg(&x[b * F_FIELDS + (lid & 15)]);

    const float4* __restrict__ W4 = reinterpret_cast<const float4*>(W);
    float4* __restrict__ out4 =
        reinterpret_cast<float4*>(out) + (size_t)b * OUT_F4;

    // 68 units per block: 4 full iterations of 16 stripes + 4 extra units
    #pragma unroll
    for (int it = 0; it < 5; ++it) {
        const int u = base + w + it * 16;
        if (it == 4 && w >= (UNITS_PER_BLK - 64)) break;   // last 4 stripes only
        if (u < N_PAIRS) {
            const unsigned int pt = c_pair[u];
            const int i = (int)(pt & 0xFF);
            const int j = (int)(pt >> 8);
            const int xi = __shfl_sync(0xFFFFFFFFu, myx, i);
            const int xj = __shfl_sync(0xFFFFFFFFu, myx, j);
            const size_t offA = ((size_t)j * V_VOCAB + (size_t)xi) * ROW_F4 + lane;
            const size_t offB = ((size_t)i * V_VOCAB + (size_t)xj) * ROW_F4 + lane;
            const float4 a  = __ldg(&W4[offA]);
            const float4 bb = __ldg(&W4[offB]);
            float4 r;
            r.x = a.x * bb.x;
            r.y = a.y * bb.y;
            r.z = a.z * bb.z;
            r.w = a.w * bb.w;
            __stcs(&out4[(size_t)u * ROW_F4 + lane], r);
        } else {
            const int f = u - N_PAIRS;
            const int xf = __shfl_sync(0xFFFFFFFFu, myx, f);
            const size_t off = ((size_t)f * V_VOCAB + (size_t)xf) * ROW_F4 + lane;
            const float4 v = __ldg(&W4[off]);
            __stcs(&out4[(size_t)u * ROW_F4 + lane], v);
        }
    }
}

extern "C" void kernel_launch(void* const* d_in, const int* in_sizes, int n_in,
                              void* d_out, int out_size)
{
    const int*   x = (const int*)d_in[0];
    const float* W = (const float*)d_in[1];
    float*       o = (float*)d_out;

    const int B = in_sizes[0] / F_FIELDS;   // 4096

    dim3 grid(B, 2);
    ffm_interact_kernel<<<grid, 256>>>(x, W, o);
}